// round 1
// baseline (speedup 1.0000x reference)
#include <cuda_runtime.h>

#define NPTS 65536
#define NCH 76          // 4*19
#define NF 64
#define NTILE 256       // 16x16 tiles of 16x16 points
#define NWORDS 2048     // 65536/32

__device__ float    g_feats[NF * NPTS];      // [f][n]
__device__ float    g_tilemax[NTILE * NF];   // [tile][f]
__device__ unsigned g_masks[NCH * NWORDS];   // [ch][word]
__device__ int      g_popcnt[NCH];
__device__ float    g_z[NCH * NF];           // [b][c][f] contiguous

__device__ __forceinline__ float lrelu(float a) { return fmaxf(a, 0.01f * a); }

// ---------------- init popcounts ----------------
__global__ void k_init() {
    int t = threadIdx.x;
    if (t < NCH) g_popcnt[t] = 0;
}

// ---------------- pack masks + popcount ----------------
__global__ __launch_bounds__(256) void k_pack(const int* __restrict__ x) {
    int g = blockIdx.x * 256 + threadIdx.x;   // g < NCH*NPTS
    int v = (x[g] == 1);
    unsigned ball = __ballot_sync(0xffffffffu, v);
    int lane = threadIdx.x & 31;
    int wp = threadIdx.x >> 5;
    __shared__ int s[8];
    if (lane == 0) {
        g_masks[g >> 5] = ball;
        s[wp] = __popc(ball);
    }
    __syncthreads();
    if (threadIdx.x == 0) {
        int tot = 0;
#pragma unroll
        for (int i = 0; i < 8; i++) tot += s[i];
        atomicAdd(&g_popcnt[g >> 16], tot);   // block fully inside one channel
    }
}

// ---------------- MLP over all grid points + tile maxima ----------------
__global__ __launch_bounds__(256) void k_mlp(
    const float* __restrict__ grid,
    const float* __restrict__ w1, const float* __restrict__ b1,
    const float* __restrict__ w2, const float* __restrict__ b2,
    const float* __restrict__ w3, const float* __restrict__ b3)
{
    __shared__ float sw1[128], sb1[64], sb2[64], sb3[64];
    __shared__ float4 sw2[1024], sw3[1024];
    __shared__ float swm[8 * 64];

    int tid = threadIdx.x;
    for (int i = tid; i < 128; i += 256) sw1[i] = w1[i];
    if (tid < 64) { sb1[tid] = b1[tid]; sb2[tid] = b2[tid]; sb3[tid] = b3[tid]; }
    for (int i = tid; i < 1024; i += 256) {
        sw2[i] = ((const float4*)w2)[i];
        sw3[i] = ((const float4*)w3)[i];
    }
    __syncthreads();

    int t = blockIdx.x;           // tile id
    int tv = t >> 4, tu = t & 15;
    int r = tid >> 4, c = tid & 15;
    int n = (tv * 16 + r) * 256 + tu * 16 + c;

    float u = grid[n], v = grid[NPTS + n];

    float za[64], zb[64];
#pragma unroll
    for (int k = 0; k < 64; k++) {
        float a = sw1[2 * k] * u + sw1[2 * k + 1] * v + sb1[k];
        za[k] = lrelu(a);
    }
    // layer 2: zb = lrelu(W2 @ za + b2)
    for (int k = 0; k < 64; k++) {
        float a0 = 0.f, a1 = 0.f, a2 = 0.f, a3 = 0.f;
#pragma unroll
        for (int j = 0; j < 16; j++) {
            float4 w = sw2[k * 16 + j];
            a0 += w.x * za[4 * j + 0];
            a1 += w.y * za[4 * j + 1];
            a2 += w.z * za[4 * j + 2];
            a3 += w.w * za[4 * j + 3];
        }
        zb[k] = lrelu((a0 + a1) + (a2 + a3) + sb2[k]);
    }
    // layer 3: za = lrelu(W3 @ zb + b3)
    for (int k = 0; k < 64; k++) {
        float a0 = 0.f, a1 = 0.f, a2 = 0.f, a3 = 0.f;
#pragma unroll
        for (int j = 0; j < 16; j++) {
            float4 w = sw3[k * 16 + j];
            a0 += w.x * zb[4 * j + 0];
            a1 += w.y * zb[4 * j + 1];
            a2 += w.z * zb[4 * j + 2];
            a3 += w.w * zb[4 * j + 3];
        }
        za[k] = lrelu((a0 + a1) + (a2 + a3) + sb3[k]);
    }

    int lane = tid & 31, wp = tid >> 5;
#pragma unroll
    for (int k = 0; k < 64; k++) {
        g_feats[k * NPTS + n] = za[k];
        float m = za[k];
        m = fmaxf(m, __shfl_xor_sync(0xffffffffu, m, 16));
        m = fmaxf(m, __shfl_xor_sync(0xffffffffu, m, 8));
        m = fmaxf(m, __shfl_xor_sync(0xffffffffu, m, 4));
        m = fmaxf(m, __shfl_xor_sync(0xffffffffu, m, 2));
        m = fmaxf(m, __shfl_xor_sync(0xffffffffu, m, 1));
        if (lane == 0) swm[wp * 64 + k] = m;
    }
    __syncthreads();
    if (tid < 64) {
        float m = swm[tid];
#pragma unroll
        for (int w = 1; w < 8; w++) m = fmaxf(m, swm[w * 64 + tid]);
        g_tilemax[t * 64 + tid] = m;
    }
}

// ---------------- masked max with tile pruning ----------------
__device__ __forceinline__ float scan_tile(int t, const float* __restrict__ fp,
                                           const unsigned* msk) {
    int tv = t >> 4, tu = t & 15;
    float m = -1e30f;
#pragma unroll 4
    for (int r = 0; r < 16; r++) {
        int nb = (tv * 16 + r) * 256 + tu * 16;
        unsigned bits = (msk[nb >> 5] >> (nb & 31)) & 0xFFFFu;
        while (bits) {
            int i = __ffs(bits) - 1;
            bits &= bits - 1;
            m = fmaxf(m, __ldg(fp + nb + i));
        }
    }
    return m;
}

__global__ __launch_bounds__(64) void k_query(
    const float* __restrict__ b1,
    const float* __restrict__ w2, const float* __restrict__ b2,
    const float* __restrict__ w3, const float* __restrict__ b3)
{
    __shared__ unsigned msk[NWORDS];
    __shared__ float z1s[64], z2s[64];

    int tid = threadIdx.x;
    int ch = blockIdx.x;
    const unsigned* gm = g_masks + ch * NWORDS;
    for (int i = tid; i < NWORDS; i += 64) msk[i] = gm[i];

    // zero-point feature (fallback for empty mask), computed cooperatively
    z1s[tid] = lrelu(b1[tid]);
    __syncthreads();
    {
        float acc = b2[tid];
#pragma unroll
        for (int j = 0; j < 64; j++) acc += w2[tid * 64 + j] * z1s[j];
        z2s[tid] = lrelu(acc);
    }
    __syncthreads();
    float zf;
    {
        float acc = b3[tid];
#pragma unroll
        for (int j = 0; j < 64; j++) acc += w3[tid * 64 + j] * z2s[j];
        zf = lrelu(acc);
    }

    int pc = g_popcnt[ch];
    int f = tid;
    const float* fp = g_feats + f * NPTS;

    float best;
    if (pc > 0) {
        // seed: tile with max unmasked feature value
        int jb = 0;
        float vb = -1e30f;
#pragma unroll 4
        for (int t2 = 0; t2 < NTILE; t2++) {
            float tm = __ldg(&g_tilemax[t2 * 64 + f]);
            if (tm > vb) { vb = tm; jb = t2; }
        }
        best = scan_tile(jb, fp, msk);
        // prune: only tiles whose (unmasked) max can beat current best
        for (int t2 = 0; t2 < NTILE; t2++) {
            if (t2 == jb) continue;
            if (__ldg(&g_tilemax[t2 * 64 + f]) > best)
                best = fmaxf(best, scan_tile(t2, fp, msk));
        }
    } else {
        best = zf;
    }
    g_z[ch * 64 + f] = best;
}

// ---------------- final FC + repeat 18 ----------------
__global__ __launch_bounds__(128) void k_fc(const float* __restrict__ fcw,
                                            const float* __restrict__ fcb,
                                            float* __restrict__ out)
{
    __shared__ float fs[4 * 1216];
    __shared__ float rw[4][4];

    int tid = threadIdx.x;
    int o = blockIdx.x;
    for (int i = tid; i < 4 * 1216; i += 128) fs[i] = g_z[i];
    __syncthreads();

    float p0 = 0.f, p1 = 0.f, p2 = 0.f, p3 = 0.f;
    const float* wr = fcw + o * 1216;
    for (int k = tid; k < 1216; k += 128) {
        float w = wr[k];
        p0 += w * fs[k];
        p1 += w * fs[1216 + k];
        p2 += w * fs[2432 + k];
        p3 += w * fs[3648 + k];
    }
#pragma unroll
    for (int off = 16; off; off >>= 1) {
        p0 += __shfl_xor_sync(0xffffffffu, p0, off);
        p1 += __shfl_xor_sync(0xffffffffu, p1, off);
        p2 += __shfl_xor_sync(0xffffffffu, p2, off);
        p3 += __shfl_xor_sync(0xffffffffu, p3, off);
    }
    int lane = tid & 31, wp = tid >> 5;
    if (lane == 0) { rw[wp][0] = p0; rw[wp][1] = p1; rw[wp][2] = p2; rw[wp][3] = p3; }
    __syncthreads();
    if (tid < 4) {
        float s = rw[0][tid] + rw[1][tid] + rw[2][tid] + rw[3][tid];
        float scale = rsqrtf(1216.0f);
        float val = s * scale + fcb[o];
#pragma unroll
        for (int r = 0; r < 18; r++)
            out[(tid * 18 + r) * 512 + o] = val;
    }
}

extern "C" void kernel_launch(void* const* d_in, const int* in_sizes, int n_in,
                              void* d_out, int out_size) {
    const int*   x    = (const int*)d_in[0];
    const float* grid = (const float*)d_in[1];
    const float* w1   = (const float*)d_in[2];
    const float* b1   = (const float*)d_in[3];
    const float* w2   = (const float*)d_in[4];
    const float* b2   = (const float*)d_in[5];
    const float* w3   = (const float*)d_in[6];
    const float* b3   = (const float*)d_in[7];
    const float* fcw  = (const float*)d_in[8];
    const float* fcb  = (const float*)d_in[9];
    float* out = (float*)d_out;

    k_init<<<1, 128>>>();
    k_pack<<<NCH * NPTS / 256, 256>>>(x);
    k_mlp<<<NTILE, 256>>>(grid, w1, b1, w2, b2, w3, b3);
    k_query<<<NCH, 64>>>(b1, w2, b2, w3, b3);
    k_fc<<<512, 128>>>(fcw, fcb, out);
}

// round 2
// speedup vs baseline: 1.6026x; 1.6026x over previous
#include <cuda_runtime.h>

#define NPTS 65536
#define NCH 76          // 4*19
#define NF 64
#define NWORDS 2048     // 65536/32
#define CHP 19          // channels per pass in k_query (4 passes)

typedef unsigned long long u64;

__device__ float    g_feats[(size_t)NPTS * NF];  // [n][f] point-major
__device__ unsigned g_masks[NCH * NWORDS];       // [ch][word]
__device__ int      g_popcnt[NCH];
__device__ unsigned g_zkey[NCH * NF];            // ordered-uint max keys
__device__ float    g_zf[NF];                    // zero-point fallback feature

__device__ __forceinline__ float lrelu(float a) { return fmaxf(a, 0.01f * a); }

// monotonic float -> uint key (radix-sort trick); atomicMax(uint) == float max
__device__ __forceinline__ unsigned okey(float f) {
    unsigned u = __float_as_uint(f);
    return u ^ (unsigned)(((int)u >> 31) | (int)0x80000000);
}
__device__ __forceinline__ float dekey(unsigned k) {
    unsigned u = (k & 0x80000000u) ? (k ^ 0x80000000u) : ~k;
    return __uint_as_float(u);
}

// ---- packed f32x2 helpers (sm_100+) ----
__device__ __forceinline__ u64 pk(float lo, float hi) {
    u64 r; asm("mov.b64 %0, {%1,%2};" : "=l"(r) : "f"(lo), "f"(hi)); return r;
}
__device__ __forceinline__ void unpk(u64 a, float& lo, float& hi) {
    asm("mov.b64 {%0,%1}, %2;" : "=f"(lo), "=f"(hi) : "l"(a));
}
__device__ __forceinline__ u64 ffma2(u64 a, u64 b, u64 c) {
    u64 d; asm("fma.rn.f32x2 %0, %1, %2, %3;" : "=l"(d) : "l"(a), "l"(b), "l"(c));
    return d;
}

// ---------------- init: popcnt=0, zkey=0, zero-point feature ----------------
__global__ void k_init(const float* __restrict__ b1,
                       const float* __restrict__ w2, const float* __restrict__ b2,
                       const float* __restrict__ w3, const float* __restrict__ b3) {
    __shared__ float z1[64], z2[64];
    int tid = threadIdx.x;
    if (tid < NCH) g_popcnt[tid] = 0;
    for (int i = tid; i < NCH * NF; i += 256) g_zkey[i] = 0u;
    if (tid < 64) z1[tid] = lrelu(b1[tid]);
    __syncthreads();
    if (tid < 64) {
        float a = b2[tid];
        for (int j = 0; j < 64; j++) a += w2[tid * 64 + j] * z1[j];
        z2[tid] = lrelu(a);
    }
    __syncthreads();
    if (tid < 64) {
        float a = b3[tid];
        for (int j = 0; j < 64; j++) a += w3[tid * 64 + j] * z2[j];
        g_zf[tid] = lrelu(a);
    }
}

// ---------------- pack masks + popcount ----------------
__global__ __launch_bounds__(256) void k_pack(const int* __restrict__ x) {
    int g = blockIdx.x * 256 + threadIdx.x;   // g < NCH*NPTS
    int v = (x[g] == 1);
    unsigned ball = __ballot_sync(0xffffffffu, v);
    int lane = threadIdx.x & 31;
    int wp = threadIdx.x >> 5;
    __shared__ int s[8];
    if (lane == 0) {
        g_masks[g >> 5] = ball;
        s[wp] = __popc(ball);
    }
    __syncthreads();
    if (threadIdx.x == 0) {
        int tot = 0;
#pragma unroll
        for (int i = 0; i < 8; i++) tot += s[i];
        atomicAdd(&g_popcnt[g >> 16], tot);   // block fully inside one channel
    }
}

// ---------------- MLP over all grid points (FFMA2 packed over j) ----------------
__global__ __launch_bounds__(128) void k_mlp(
    const float* __restrict__ grid,
    const float* __restrict__ w1, const float* __restrict__ b1,
    const float* __restrict__ w2, const float* __restrict__ b2,
    const float* __restrict__ w3, const float* __restrict__ b3)
{
    __shared__ float sw1[128], sb1[64], sb2[64], sb3[64];
    __shared__ u64 sw2q[2048], sw3q[2048];   // raw rows of w2/w3 viewed as f32 pairs

    int tid = threadIdx.x;
    sw1[tid] = w1[tid];
    if (tid < 64) { sb1[tid] = b1[tid]; sb2[tid] = b2[tid]; sb3[tid] = b3[tid]; }
    for (int i = tid; i < 2048; i += 128) {
        sw2q[i] = ((const u64*)w2)[i];
        sw3q[i] = ((const u64*)w3)[i];
    }
    __syncthreads();

    int n = blockIdx.x * 128 + tid;
    float uu = grid[n], vv = grid[NPTS + n];

    // layer 1 -> packed activations zq[k] = (z[2k], z[2k+1])
    u64 zq[32];
#pragma unroll
    for (int k = 0; k < 32; k++) {
        float a0 = fmaf(sw1[4 * k + 0], uu, fmaf(sw1[4 * k + 1], vv, sb1[2 * k]));
        float a1 = fmaf(sw1[4 * k + 2], uu, fmaf(sw1[4 * k + 3], vv, sb1[2 * k + 1]));
        zq[k] = pk(lrelu(a0), lrelu(a1));
    }

    float zs[64];
    // layer 2
#pragma unroll
    for (int k = 0; k < 64; k++) {
        const ulonglong2* wr = (const ulonglong2*)(sw2q + k * 32);
        u64 a0 = 0ull, a1 = 0ull;
#pragma unroll
        for (int j2 = 0; j2 < 16; j2++) {
            ulonglong2 wv = wr[j2];
            a0 = ffma2(wv.x, zq[2 * j2 + 0], a0);
            a1 = ffma2(wv.y, zq[2 * j2 + 1], a1);
        }
        float l0, h0, l1, h1;
        unpk(a0, l0, h0); unpk(a1, l1, h1);
        zs[k] = lrelu((l0 + h0) + (l1 + h1) + sb2[k]);
    }
#pragma unroll
    for (int k = 0; k < 32; k++) zq[k] = pk(zs[2 * k], zs[2 * k + 1]);

    // layer 3
#pragma unroll
    for (int k = 0; k < 64; k++) {
        const ulonglong2* wr = (const ulonglong2*)(sw3q + k * 32);
        u64 a0 = 0ull, a1 = 0ull;
#pragma unroll
        for (int j2 = 0; j2 < 16; j2++) {
            ulonglong2 wv = wr[j2];
            a0 = ffma2(wv.x, zq[2 * j2 + 0], a0);
            a1 = ffma2(wv.y, zq[2 * j2 + 1], a1);
        }
        float l0, h0, l1, h1;
        unpk(a0, l0, h0); unpk(a1, l1, h1);
        zs[k] = lrelu((l0 + h0) + (l1 + h1) + sb3[k]);
    }

    // store point-major [n][64]
    float4* op = (float4*)(g_feats + (size_t)n * 64);
#pragma unroll
    for (int k = 0; k < 16; k++)
        op[k] = make_float4(zs[4 * k], zs[4 * k + 1], zs[4 * k + 2], zs[4 * k + 3]);
}

// ---------------- brute-force masked max, channel-register passes ----------------
__global__ __launch_bounds__(256) void k_query() {
    __shared__ unsigned smask[NCH * 8];     // mask words for this block's 256 points
    __shared__ float sred[4][CHP][64];

    int tid = threadIdx.x;
    int f = tid & 63, g = tid >> 6;         // 4 groups of 64 points
    int blk = blockIdx.x;

    for (int i = tid; i < NCH * 8; i += 256)
        smask[i] = g_masks[(i >> 3) * NWORDS + blk * 8 + (i & 7)];
    __syncthreads();

    const float* fp = g_feats;

    for (int p = 0; p < 4; p++) {
        int ch0 = p * CHP;
        float acc[CHP];
#pragma unroll
        for (int j = 0; j < CHP; j++) acc[j] = -3.402823466e38f;

        for (int b = 0; b < 2; b++) {
            int nb = blk * 256 + g * 64 + b * 32;
            float v[32];
#pragma unroll
            for (int i = 0; i < 32; i++)
                v[i] = __ldg(fp + (size_t)(nb + i) * 64 + f);
            unsigned wd[CHP];
#pragma unroll
            for (int j = 0; j < CHP; j++)
                wd[j] = smask[(ch0 + j) * 8 + g * 2 + b];
#pragma unroll
            for (int i = 0; i < 32; i++) {
#pragma unroll
                for (int j = 0; j < CHP; j++)
                    if (wd[j] & (1u << i)) acc[j] = fmaxf(acc[j], v[i]);
            }
        }

#pragma unroll
        for (int j = 0; j < CHP; j++) sred[g][j][f] = acc[j];
        __syncthreads();
        for (int q = tid; q < CHP * 64; q += 256) {
            int j = q >> 6, f2 = q & 63;
            float m = fmaxf(fmaxf(sred[0][j][f2], sred[1][j][f2]),
                            fmaxf(sred[2][j][f2], sred[3][j][f2]));
            atomicMax(&g_zkey[(ch0 + j) * 64 + f2], okey(m));
        }
        __syncthreads();
    }
}

// ---------------- final FC + repeat 18 ----------------
__global__ __launch_bounds__(128) void k_fc(const float* __restrict__ fcw,
                                            const float* __restrict__ fcb,
                                            float* __restrict__ out)
{
    __shared__ float fs[NCH * NF];
    __shared__ float rw[4][4];

    int tid = threadIdx.x;
    int o = blockIdx.x;
    for (int i = tid; i < NCH * NF; i += 128) {
        int ch = i >> 6;
        fs[i] = (g_popcnt[ch] > 0) ? dekey(g_zkey[i]) : g_zf[i & 63];
    }
    __syncthreads();

    float p0 = 0.f, p1 = 0.f, p2 = 0.f, p3 = 0.f;
    const float* wr = fcw + o * 1216;
    for (int k = tid; k < 1216; k += 128) {
        float w = wr[k];
        p0 += w * fs[k];
        p1 += w * fs[1216 + k];
        p2 += w * fs[2432 + k];
        p3 += w * fs[3648 + k];
    }
#pragma unroll
    for (int off = 16; off; off >>= 1) {
        p0 += __shfl_xor_sync(0xffffffffu, p0, off);
        p1 += __shfl_xor_sync(0xffffffffu, p1, off);
        p2 += __shfl_xor_sync(0xffffffffu, p2, off);
        p3 += __shfl_xor_sync(0xffffffffu, p3, off);
    }
    int lane = tid & 31, wp = tid >> 5;
    if (lane == 0) { rw[wp][0] = p0; rw[wp][1] = p1; rw[wp][2] = p2; rw[wp][3] = p3; }
    __syncthreads();
    if (tid < 4) {
        float s = rw[0][tid] + rw[1][tid] + rw[2][tid] + rw[3][tid];
        float scale = rsqrtf(1216.0f);
        float val = s * scale + fcb[o];
#pragma unroll
        for (int r = 0; r < 18; r++)
            out[(tid * 18 + r) * 512 + o] = val;
    }
}

extern "C" void kernel_launch(void* const* d_in, const int* in_sizes, int n_in,
                              void* d_out, int out_size) {
    const int*   x    = (const int*)d_in[0];
    const float* grid = (const float*)d_in[1];
    const float* w1   = (const float*)d_in[2];
    const float* b1   = (const float*)d_in[3];
    const float* w2   = (const float*)d_in[4];
    const float* b2   = (const float*)d_in[5];
    const float* w3   = (const float*)d_in[6];
    const float* b3   = (const float*)d_in[7];
    const float* fcw  = (const float*)d_in[8];
    const float* fcb  = (const float*)d_in[9];
    float* out = (float*)d_out;

    k_init<<<1, 256>>>(b1, w2, b2, w3, b3);
    k_pack<<<NCH * NPTS / 256, 256>>>(x);
    k_mlp<<<NPTS / 128, 128>>>(grid, w1, b1, w2, b2, w3, b3);
    k_query<<<NPTS / 256, 256>>>();
    k_fc<<<512, 128>>>(fcw, fcb, out);
}